// round 9
// baseline (speedup 1.0000x reference)
#include <cuda_runtime.h>

#define BDIM 512
#define FDIM 1024
#define H1D  512
#define H2D  256
#define OUTD 128
#define KDD  5
#define NMD  (OUTD*KDD)   // 640
#define LOG2E 1.44269504f
#define NB   296          // 2 blocks/SM on 148 SMs, all co-resident

// Scratch (device globals)
__device__ float g_h1p[8 * BDIM * H1D];    // GEMM1 partials (split-K=8)
__device__ float g_h1 [BDIM * H1D];
__device__ float g_h2p[8 * BDIM * H2D];    // GEMM2 partials (split-K=8)
__device__ float g_h2 [BDIM * H2D];
__device__ float g_Mp [4 * BDIM * NMD];    // GEMM3 partials (split-K=4)
__device__ float g_M  [BDIM * NMD];        // reduced M, pre-scaled by log2e
__device__ float g_ob [OUTD * BDIM];       // pairwise output [o][j] (incl. +1 self)
__device__ float g_z3p[6 * BDIM * OUTD];   // GEMM4 partials (4 h2 + 2 ob)

// Tile-completion counters (atomicInc with wrap -> self-reset across replays)
__device__ unsigned g_c1[32];
__device__ unsigned g_c2[16];
__device__ unsigned g_c3[40];
__device__ unsigned g_barcount = 0;
__device__ volatile unsigned g_bargen = 0;

__device__ __forceinline__ float lrelu(float v) { return fmaxf(v, 0.2f * v); }

#define FMA2(c, a, b) asm("fma.rn.f32x2 %0, %1, %2, %0;" : "+l"(c) : "l"(a), "l"(b))

// smem layout (union of phases), 41988 B static
// GEMM:  A2: 2 bufs x 16 k x 130 float2 (pre-duplicated pairs) = 33280 B
//        Bs: 2 bufs x 16 k x 68  float                          = 8704 B
// Pairwise: s4: 512 float4 (8192 B) + s1: 512 float (2048 B)
#define A2_BUF  2080            // float2 elements per buffer (16*130)
#define BS_BUF  1088            // floats per buffer (16*68)
#define SM_BYTES (33280 + 8704)

__device__ __forceinline__ void grid_barrier()
{
    __syncthreads();
    if (threadIdx.x == 0) {
        unsigned gen = g_bargen;
        __threadfence();
        if (atomicInc(&g_barcount, NB - 1) == NB - 1) {
            __threadfence();
            g_bargen = gen + 1;
        } else {
            while (g_bargen == gen) __nanosleep(64);
            __threadfence();
        }
    }
    __syncthreads();
}

// ---------------------------------------------------------------------------
// 128(M) x 64(N) x Kc GEMM tile, 256 threads, BK=16, 4m x 8n f32x2 microtile.
// A staged in smem as duplicated f32x2 pairs -> inner loop is 4 LDS.128 +
// 16 FFMA2 per kk per thread, no splat MOVs. Double-buffered, reg prefetch.
// OB=1: A is k-major [k][m] (ld=512) and gets -1 applied (pairwise output).
// ---------------------------------------------------------------------------
template<int OB>
__device__ void gemm_tile(char* sm, int ux, int uy, int uz,
                          const float* __restrict__ Abase,
                          const float* __restrict__ Bm,
                          float* __restrict__ Cpart, size_t cpStride,
                          int Kc, int lda, int ldb, int ldc)
{
    float2* A2 = (float2*)sm;
    float*  Bs = (float*)(sm + 33280);

    const int tid  = threadIdx.x;
    const int tn   = (tid & 7) * 8;    // cols tn..tn+7
    const int tm   = (tid >> 3) * 4;   // rows tm..tm+3
    const int row0 = uy * 128;
    const int col0 = ux * 64;
    const int k0   = uz * Kc;

    float4 pa[2], pb;

    auto fetch = [&](int kbase) {
        #pragma unroll
        for (int i = 0; i < 2; i++) {
            int f = tid + i * 256;
            if (!OB) {
                int r = f >> 2, kq = (f & 3) * 4;
                pa[i] = *(const float4*)(Abase + (size_t)(row0 + r) * lda + kbase + kq);
            } else {
                int kk = f >> 5, mq = (f & 31) * 4;
                float4 v = *(const float4*)(Abase + (size_t)(kbase + kk) * BDIM + row0 + mq);
                v.x -= 1.0f; v.y -= 1.0f; v.z -= 1.0f; v.w -= 1.0f;
                pa[i] = v;
            }
        }
        int kk = tid >> 4, nq = (tid & 15) * 4;
        pb = *(const float4*)(Bm + (size_t)(kbase + kk) * ldb + col0 + nq);
    };
    auto stick = [&](int buf) {
        float2* A_ = A2 + buf * A2_BUF;
        #pragma unroll
        for (int i = 0; i < 2; i++) {
            int f = tid + i * 256;
            float v[4] = {pa[i].x, pa[i].y, pa[i].z, pa[i].w};
            if (!OB) {
                int r = f >> 2, kq = (f & 3) * 4;
                #pragma unroll
                for (int j = 0; j < 4; j++)
                    A_[(kq + j) * 130 + r] = make_float2(v[j], v[j]);
            } else {
                int kk = f >> 5, mq = (f & 31) * 4;
                #pragma unroll
                for (int j = 0; j < 4; j++)
                    A_[kk * 130 + mq + j] = make_float2(v[j], v[j]);
            }
        }
        int kk = tid >> 4, nq = (tid & 15) * 4;
        *(float4*)&Bs[buf * BS_BUF + kk * 68 + nq] = pb;
    };

    unsigned long long acc[4][4] = {};

    fetch(k0);
    __syncthreads();          // smem may still be read by the previous unit
    stick(0);
    __syncthreads();

    for (int kt = 0; kt < Kc; kt += 16) {
        const int  cur = (kt >> 4) & 1;
        const bool nxt = (kt + 16) < Kc;
        if (nxt) fetch(k0 + kt + 16);

        const float2* A_ = A2 + cur * A2_BUF;
        const float*  B_ = Bs + cur * BS_BUF;
        #pragma unroll
        for (int kk = 0; kk < 16; kk++) {
            ulonglong2 a01 = *(const ulonglong2*)(A_ + kk * 130 + tm);
            ulonglong2 a23 = *(const ulonglong2*)(A_ + kk * 130 + tm + 2);
            ulonglong2 b01 = *(const ulonglong2*)(B_ + kk * 68 + tn);
            ulonglong2 b23 = *(const ulonglong2*)(B_ + kk * 68 + tn + 4);
            unsigned long long av[4] = {a01.x, a01.y, a23.x, a23.y};
            unsigned long long bv[4] = {b01.x, b01.y, b23.x, b23.y};
            #pragma unroll
            for (int mi = 0; mi < 4; mi++)
                #pragma unroll
                for (int nj = 0; nj < 4; nj++)
                    FMA2(acc[mi][nj], av[mi], bv[nj]);
        }
        if (nxt) stick(cur ^ 1);
        __syncthreads();
    }

    float* cp = Cpart + (size_t)uz * cpStride;
    #pragma unroll
    for (int mi = 0; mi < 4; mi++) {
        int row = row0 + tm + mi;
        ulonglong2 v0, v1;
        v0.x = acc[mi][0]; v0.y = acc[mi][1];
        v1.x = acc[mi][2]; v1.y = acc[mi][3];
        *(ulonglong2*)&cp[(size_t)row * ldc + col0 + tn]     = v0;
        *(ulonglong2*)&cp[(size_t)row * ldc + col0 + tn + 4] = v1;
    }
}

// Last-arrival detection for a split-K tile (replay-safe: counter wraps).
__device__ __forceinline__ bool last_arrival(unsigned* cnt, unsigned wrap, int* sflag)
{
    __threadfence();
    __syncthreads();
    if (threadIdx.x == 0) *sflag = (atomicInc(cnt, wrap) == wrap);
    __syncthreads();
    bool last = (*sflag != 0);
    if (last && threadIdx.x == 0) __threadfence();
    return last;
}

// Reduce SPLIT partials for one 128x64 tile. MODE 0: +bias, lrelu. MODE 1: *log2e.
template<int SPLIT, int MODE>
__device__ void reduce_tile(const float* __restrict__ P, size_t st,
                            const float* __restrict__ bias,
                            float* __restrict__ Out,
                            int row0, int col0, int ldc)
{
    const int tid = threadIdx.x;
    #pragma unroll
    for (int it = 0; it < 8; it++) {
        int idx = tid + it * 256;
        int r = idx >> 4, c4 = (idx & 15) * 4;
        const float* p = P + (size_t)(row0 + r) * ldc + col0 + c4;
        float4 v = *(const float4*)p;
        #pragma unroll
        for (int s = 1; s < SPLIT; s++) {
            float4 u = *(const float4*)(p + (size_t)s * st);
            v.x += u.x; v.y += u.y; v.z += u.z; v.w += u.w;
        }
        if (MODE == 0) {
            float4 bv = *(const float4*)(bias + col0 + c4);
            v.x = lrelu(v.x + bv.x);
            v.y = lrelu(v.y + bv.y);
            v.z = lrelu(v.z + bv.z);
            v.w = lrelu(v.w + bv.w);
        } else {
            v.x *= LOG2E; v.y *= LOG2E; v.z *= LOG2E; v.w *= LOG2E;
        }
        *(float4*)(Out + (size_t)(row0 + r) * ldc + col0 + c4) = v;
    }
}

// One pairwise unit: column o, j-block of 256. Full i loop (512).
__device__ void pairwise_unit(char* sm, int o, int jh)
{
    float4* s4 = (float4*)sm;            // 512 x float4 (M[:,o,0..3] * log2e)
    float*  s1 = (float*)(sm + 8192);    // 512 x float  (M[:,o,4]    * log2e)
    const int tid = threadIdx.x;

    __syncthreads();   // previous unit may still read smem (none here, but safe)
    #pragma unroll
    for (int it = 0; it < 10; it++) {
        int idx = tid + it * 256;        // 0..2559
        int i = idx / 5, k = idx - i * 5;
        float val = g_M[(size_t)i * NMD + o * KDD + k];
        if (k < 4) ((float*)s4)[i * 4 + k] = val;
        else       s1[i] = val;
    }
    __syncthreads();

    const int j = jh * 256 + tid;
    float4 m4 = s4[j];
    float  m4e = s1[j];

    float acc0 = 0.f, acc1 = 0.f;
    #pragma unroll 8
    for (int i = 0; i < BDIM; i++) {
        float4 v = s4[i];
        float  w = s1[i];
        float n = fabsf(v.x - m4.x) + fabsf(v.y - m4.y) + fabsf(v.z - m4.z)
                + fabsf(v.w - m4.w) + fabsf(w - m4e);
        float e;
        asm("ex2.approx.f32 %0, %1;" : "=f"(e) : "f"(-n));
        if (i & 1) acc1 += e; else acc0 += e;
    }
    g_ob[o * BDIM + j] = acc0 + acc1;    // includes self term; -1 applied in G4b
}

// ---------------------------------------------------------------------------
__global__ __launch_bounds__(256, 2)
void mega(const float* __restrict__ x,  const float* __restrict__ W1,
          const float* __restrict__ b1, const float* __restrict__ W2,
          const float* __restrict__ b2, const float* __restrict__ T,
          const float* __restrict__ W3, const float* __restrict__ b3,
          const float* __restrict__ W4, const float* __restrict__ b4,
          float* __restrict__ out)
{
    __shared__ __align__(16) char sm[SM_BYTES];
    __shared__ int sflag;
    const int bid = blockIdx.x;
    const int tid = threadIdx.x;

    // P1: GEMM1 x@W1 -> h1p (split-K=8, Kc=128), 8x4x8 = 256 units.
    // Last split block per tile reduces 8 partials + b1 + lrelu -> h1.
    if (bid < 256) {
        int ux = bid & 7, uy = (bid >> 3) & 3, uz = bid >> 5;
        gemm_tile<0>(sm, ux, uy, uz, x, W1,
                     g_h1p, (size_t)BDIM * H1D, 128, FDIM, H1D, H1D);
        if (last_arrival(&g_c1[uy * 8 + ux], 7, &sflag))
            reduce_tile<8, 0>(g_h1p, (size_t)BDIM * H1D, b1, g_h1,
                              uy * 128, ux * 64, H1D);
    }
    grid_barrier();

    // P2: GEMM2 h1@W2 -> h2p (split-K=8, Kc=64), 4x4x8 = 128 units. Self-reduce -> h2.
    if (bid < 128) {
        int ux = bid & 3, uy = (bid >> 2) & 3, uz = bid >> 4;
        gemm_tile<0>(sm, ux, uy, uz, g_h1, W2,
                     g_h2p, (size_t)BDIM * H2D, 64, H1D, H2D, H2D);
        if (last_arrival(&g_c2[uy * 4 + ux], 7, &sflag))
            reduce_tile<8, 0>(g_h2p, (size_t)BDIM * H2D, b2, g_h2,
                              uy * 128, ux * 64, H2D);
    }
    grid_barrier();

    // P3: GEMM3 h2@T -> Mp (split-K=4, Kc=64), 10x4x4 = 160 units.
    // Self-reduce (x log2e) -> M.
    if (bid < 160) {
        int ux = bid % 10, uy = (bid / 10) & 3, uz = bid / 40;
        gemm_tile<0>(sm, ux, uy, uz, g_h2, T,
                     g_Mp, (size_t)BDIM * NMD, 64, H2D, NMD, NMD);
        if (last_arrival(&g_c3[uy * 10 + ux], 3, &sflag))
            reduce_tile<4, 1>(g_Mp, (size_t)BDIM * NMD, nullptr, g_M,
                              uy * 128, ux * 64, NMD);
    }
    grid_barrier();

    // P4: pairwise (256 units) overlapped with GEMM4a h2@W3[:256] -> z3p[0..3]
    //     (split-K=4, Kc=64, 32 units). 288 units total.
    if (bid < 256) {
        pairwise_unit(sm, bid & 127, bid >> 7);
    } else if (bid < 288) {
        int v = bid - 256;
        int ux = v & 1, uy = (v >> 1) & 3, uz = v >> 3;
        gemm_tile<0>(sm, ux, uy, uz, g_h2, W3,
                     g_z3p, (size_t)BDIM * OUTD, 64, H2D, OUTD, OUTD);
    }
    grid_barrier();

    // P5: GEMM4b (ob-1)@W3[256:] -> z3p[4..5] (split-K=2, Kc=64), 16 units.
    if (bid < 16) {
        int ux = bid & 1, uy = (bid >> 1) & 3, uz = bid >> 3;
        gemm_tile<1>(sm, ux, uy, uz, g_ob, W3 + 256 * OUTD,
                     g_z3p + 4 * (size_t)BDIM * OUTD, (size_t)BDIM * OUTD,
                     64, 0, OUTD, OUTD);
    }
    grid_barrier();

    // P6: final — z3 = lrelu(sum6 z3p + b3); out = z3@W4 + b4. One warp/row.
    if (bid < 64) {
        const size_t ZS = (size_t)BDIM * OUTD;
        int gw   = bid * 8 + (tid >> 5);
        int lane = tid & 31;
        float sum = 0.f;
        #pragma unroll
        for (int it = 0; it < 4; it++) {
            int k = it * 32 + lane;
            const float* p = g_z3p + (size_t)gw * OUTD + k;
            float v = ((p[0] + p[ZS]) + (p[2 * ZS] + p[3 * ZS]))
                    + (p[4 * ZS] + p[5 * ZS]) + b3[k];
            v = lrelu(v);
            sum += v * W4[k];
        }
        #pragma unroll
        for (int off = 16; off; off >>= 1)
            sum += __shfl_xor_sync(0xffffffffu, sum, off);
        if (lane == 0) out[gw] = sum + b4[0];
    }
}

// ---------------------------------------------------------------------------
extern "C" void kernel_launch(void* const* d_in, const int* in_sizes, int n_in,
                              void* d_out, int out_size)
{
    (void)in_sizes; (void)n_in; (void)out_size;
    mega<<<NB, 256>>>((const float*)d_in[0], (const float*)d_in[1],
                      (const float*)d_in[2], (const float*)d_in[3],
                      (const float*)d_in[4], (const float*)d_in[5],
                      (const float*)d_in[6], (const float*)d_in[7],
                      (const float*)d_in[8], (const float*)d_in[9],
                      (float*)d_out);
}

// round 11
// speedup vs baseline: 1.8590x; 1.8590x over previous
#include <cuda_runtime.h>
#include <cuda_bf16.h>
#include <cstdint>

#define BDIM 512
#define FDIM 1024
#define H1D  512
#define H2D  256
#define OUTD 128
#define KDD  5
#define NMD  (OUTD*KDD)   // 640
#define ZD   384
#define LOG2E 1.44269504f

// Prepped weights: bf16 hi/lo, transposed to [n][k]
#define WOFF_W1 0
#define WOFF_W2 524288            // +512*1024
#define WOFF_T  655360            // +256*512
#define WOFF_W3 819200            // +640*256
#define WTOT    868352            // +128*384
__device__ __nv_bfloat16 g_Wbh[WTOT];
__device__ __nv_bfloat16 g_Wbl[WTOT];

// Activations / partials
__device__ float g_p1[4 * BDIM * H1D];
__device__ float g_h1[BDIM * H1D];
__device__ float g_p2[4 * BDIM * H2D];
__device__ float g_z [BDIM * ZD];      // cols 0..255 = h2, 256..383 = o_b
__device__ float g_p3[2 * BDIM * NMD];
__device__ float g_M [BDIM * NMD];     // prescaled by log2e
__device__ float g_p4[3 * BDIM * OUTD];
__device__ float g_z3[BDIM * OUTD];

__device__ __forceinline__ float lrelu(float v) { return fmaxf(v, 0.2f * v); }

__device__ __forceinline__ uint32_t smem_u32(const void* p) {
    uint32_t a;
    asm("{ .reg .u64 t; cvta.to.shared.u64 t, %1; cvt.u32.u64 %0, t; }"
        : "=r"(a) : "l"(p));
    return a;
}
__device__ __forceinline__ void ldmx4(uint32_t* r, uint32_t addr) {
    asm volatile("ldmatrix.sync.aligned.m8n8.x4.shared.b16 {%0,%1,%2,%3}, [%4];"
                 : "=r"(r[0]), "=r"(r[1]), "=r"(r[2]), "=r"(r[3]) : "r"(addr));
}
__device__ __forceinline__ void mma16816(float* d, const uint32_t* a,
                                         uint32_t b0, uint32_t b1) {
    asm volatile("mma.sync.aligned.m16n8k16.row.col.f32.bf16.bf16.f32 "
                 "{%0,%1,%2,%3}, {%4,%5,%6,%7}, {%8,%9}, {%0,%1,%2,%3};"
                 : "+f"(d[0]), "+f"(d[1]), "+f"(d[2]), "+f"(d[3])
                 : "r"(a[0]), "r"(a[1]), "r"(a[2]), "r"(a[3]), "r"(b0), "r"(b1));
}
// pack two fp32 -> bf16x2 (lo element in low half)
__device__ __forceinline__ uint32_t bf16pack(float lo_elem, float hi_elem) {
    uint32_t r;
    asm("cvt.rn.bf16x2.f32 %0, %1, %2;" : "=r"(r) : "f"(hi_elem), "f"(lo_elem));
    return r;
}

// ---------------------------------------------------------------------------
// Prep: W [K][N] fp32 -> Wbh/Wbl [n][k] bf16 (transpose + hi/lo split)
// ---------------------------------------------------------------------------
__global__ __launch_bounds__(256)
void prep_k(const float* __restrict__ W1, const float* __restrict__ W2,
            const float* __restrict__ T,  const float* __restrict__ W3)
{
    __shared__ float s[32][33];
    int b = blockIdx.x;
    const float* src; int K, N; size_t off; int rel;
    if      (b < 512) { src = W1; K = 1024; N = 512; off = WOFF_W1; rel = b; }
    else if (b < 640) { src = W2; K = 512;  N = 256; off = WOFF_W2; rel = b - 512; }
    else if (b < 800) { src = T;  K = 256;  N = 640; off = WOFF_T;  rel = b - 640; }
    else              { src = W3; K = 384;  N = 128; off = WOFF_W3; rel = b - 800; }
    int ktiles = K / 32;
    int k0 = (rel % ktiles) * 32, n0 = (rel / ktiles) * 32;
    int tx = threadIdx.x & 31, ty = threadIdx.x >> 5;

    #pragma unroll
    for (int i = 0; i < 4; i++)
        s[ty + i * 8][tx] = src[(size_t)(k0 + ty + i * 8) * N + n0 + tx];
    __syncthreads();
    #pragma unroll
    for (int i = 0; i < 4; i++) {
        int n = n0 + ty + i * 8, k = k0 + tx;
        float v = s[tx][ty + i * 8];
        __nv_bfloat16 h = __float2bfloat16_rn(v);
        float l = v - __bfloat162float(h);
        g_Wbh[off + (size_t)n * K + k] = h;
        g_Wbl[off + (size_t)n * K + k] = __float2bfloat16_rn(l);
    }
}

// ---------------------------------------------------------------------------
// Tensor-core GEMM via mma.sync bf16 3-pass (AhBh + AlBh + AhBl).
// CTA: 128(M) x 64(N), 8 warps (4m x 2n), warp tile 32x32, K-chunks of 32.
// A fp32 -> hi/lo bf16 on the fly; B from prepped [n][k] bf16.
// smem rows padded to 80 B -> conflict-free ldmatrix. Split-K via blockIdx.z.
// ---------------------------------------------------------------------------
#define SA_ST 80
#define SAH 0
#define SAL 10240
#define SBH 20480
#define SBL 25600
#define SM_TOT 30720

__global__ __launch_bounds__(256)
void tgemm(const float* __restrict__ A, int lda,
           const __nv_bfloat16* __restrict__ Bhg,
           const __nv_bfloat16* __restrict__ Blg, int Kb,
           float* __restrict__ Cpart, size_t cpStride, int ldc, int Kc)
{
    __shared__ __align__(16) char sb[SM_TOT];
    const int tid = threadIdx.x, lane = tid & 31, wid = tid >> 5;
    const int wm = wid >> 1, wn = wid & 1;
    const int n0 = blockIdx.x * 64, row0 = blockIdx.y * 128;
    const int kbase = blockIdx.z * Kc;
    const uint32_t sbase = smem_u32(sb);

    float acc[2][4][4] = {};                 // [m16][n8][reg]

    const int ar = tid >> 1, ah = tid & 1;   // A: 128 rows x 2 k-halves
    const int br = tid >> 2, bq = tid & 3;   // B: 64 rows x 4 16B-quads
    float4 pa[4]; uint4 pbh, pbl;

    auto fetch = [&](int k0) {
        const float* ap = A + (size_t)(row0 + ar) * lda + k0 + ah * 16;
        pa[0] = *(const float4*)(ap);
        pa[1] = *(const float4*)(ap + 4);
        pa[2] = *(const float4*)(ap + 8);
        pa[3] = *(const float4*)(ap + 12);
        pbh = *(const uint4*)(Bhg + (size_t)(n0 + br) * Kb + k0 + bq * 8);
        pbl = *(const uint4*)(Blg + (size_t)(n0 + br) * Kb + k0 + bq * 8);
    };
    auto stick = [&]() {
        float e[16] = {pa[0].x, pa[0].y, pa[0].z, pa[0].w,
                       pa[1].x, pa[1].y, pa[1].z, pa[1].w,
                       pa[2].x, pa[2].y, pa[2].z, pa[2].w,
                       pa[3].x, pa[3].y, pa[3].z, pa[3].w};
        uint32_t hp[8], lp[8];
        #pragma unroll
        for (int j = 0; j < 8; j++) {
            float a0 = e[2 * j], a1 = e[2 * j + 1];
            __nv_bfloat16 h0 = __float2bfloat16_rn(a0);
            __nv_bfloat16 h1 = __float2bfloat16_rn(a1);
            hp[j] = bf16pack(a0, a1);
            lp[j] = bf16pack(a0 - __bfloat162float(h0), a1 - __bfloat162float(h1));
        }
        char* da = sb + SAH + ar * SA_ST + ah * 32;
        *(uint4*)(da)      = make_uint4(hp[0], hp[1], hp[2], hp[3]);
        *(uint4*)(da + 16) = make_uint4(hp[4], hp[5], hp[6], hp[7]);
        char* dl = sb + SAL + ar * SA_ST + ah * 32;
        *(uint4*)(dl)      = make_uint4(lp[0], lp[1], lp[2], lp[3]);
        *(uint4*)(dl + 16) = make_uint4(lp[4], lp[5], lp[6], lp[7]);
        *(uint4*)(sb + SBH + br * SA_ST + bq * 16) = pbh;
        *(uint4*)(sb + SBL + br * SA_ST + bq * 16) = pbl;
    };

    fetch(kbase);
    stick();
    __syncthreads();

    const int nch = Kc / 32;
    for (int ch = 0; ch < nch; ch++) {
        const bool nxt = (ch + 1) < nch;
        if (nxt) fetch(kbase + (ch + 1) * 32);

        #pragma unroll
        for (int kt = 0; kt < 2; kt++) {
            uint32_t afh[2][4], afl[2][4], bfh[2][4], bfl[2][4];
            #pragma unroll
            for (int mt = 0; mt < 2; mt++) {
                uint32_t ad = sbase + SAH + (wm * 32 + mt * 16 + (lane & 15)) * SA_ST
                            + kt * 32 + ((lane >> 4) << 4);
                ldmx4(afh[mt], ad);
                ldmx4(afl[mt], ad + (SAL - SAH));
            }
            #pragma unroll
            for (int bt = 0; bt < 2; bt++) {
                uint32_t bd = sbase + SBH + (wn * 32 + bt * 16 + (lane & 15)) * SA_ST
                            + kt * 32 + ((lane >> 4) << 4);
                ldmx4(bfh[bt], bd);
                ldmx4(bfl[bt], bd + (SBL - SBH));
            }
            #pragma unroll
            for (int mt = 0; mt < 2; mt++)
                #pragma unroll
                for (int j = 0; j < 4; j++) {
                    int t = j >> 1, o = j & 1;
                    uint32_t b0h = bfh[t][o], b1h = bfh[t][o + 2];
                    uint32_t b0l = bfl[t][o], b1l = bfl[t][o + 2];
                    mma16816(acc[mt][j], afh[mt], b0h, b1h);
                    mma16816(acc[mt][j], afl[mt], b0h, b1h);
                    mma16816(acc[mt][j], afh[mt], b0l, b1l);
                }
        }
        __syncthreads();
        if (nxt) { stick(); __syncthreads(); }
    }

    // Epilogue: raw partial store (reduce kernel applies bias/activation)
    float* cp = Cpart + (size_t)blockIdx.z * cpStride;
    #pragma unroll
    for (int mt = 0; mt < 2; mt++)
        #pragma unroll
        for (int j = 0; j < 4; j++) {
            int r = row0 + wm * 32 + mt * 16 + (lane >> 2);
            int c = n0 + wn * 32 + j * 8 + (lane & 3) * 2;
            *(float2*)&cp[(size_t)r * ldc + c] =
                make_float2(acc[mt][j][0], acc[mt][j][1]);
            *(float2*)&cp[(size_t)(r + 8) * ldc + c] =
                make_float2(acc[mt][j][2], acc[mt][j][3]);
        }
}

// ---------------------------------------------------------------------------
// Reduce SPLIT partials. MODE 0: +bias, lrelu; MODE 1: *log2e (no bias).
// One float4 per thread; output may have different leading dim (concat).
// ---------------------------------------------------------------------------
template<int SPLIT, int MODE>
__global__ __launch_bounds__(256)
void reduce_k(const float* __restrict__ P, size_t pstride, int ncols,
              const float* __restrict__ bias,
              float* __restrict__ Out, int ld_out, int total4)
{
    int f = blockIdx.x * 256 + threadIdx.x;
    if (f >= total4) return;
    int e = f * 4;
    int row = e / ncols, c = e - row * ncols;
    const float* p = P + (size_t)row * ncols + c;
    float4 v = *(const float4*)p;
    #pragma unroll
    for (int s = 1; s < SPLIT; s++) {
        float4 u = *(const float4*)(p + (size_t)s * pstride);
        v.x += u.x; v.y += u.y; v.z += u.z; v.w += u.w;
    }
    if (MODE == 0) {
        float4 bv = *(const float4*)(bias + c);
        v.x = lrelu(v.x + bv.x);
        v.y = lrelu(v.y + bv.y);
        v.z = lrelu(v.z + bv.z);
        v.w = lrelu(v.w + bv.w);
    } else {
        v.x *= LOG2E; v.y *= LOG2E; v.z *= LOG2E; v.w *= LOG2E;
    }
    *(float4*)(Out + (size_t)row * ld_out + c) = v;
}

// ---------------------------------------------------------------------------
// Pairwise: o_b[j,o] = sum_i exp2(-|M[i,o,:]-M[j,o,:]|_1) - 1  (M prescaled)
// grid (o=128, jh=2), 256 threads. Writes z[:, 256+o].
// ---------------------------------------------------------------------------
__global__ __launch_bounds__(256)
void pairwise_k(const float* __restrict__ M, float* __restrict__ z)
{
    __shared__ float4 s4[BDIM];
    __shared__ float  s1[BDIM];
    const int o = blockIdx.x, jh = blockIdx.y;
    const int tid = threadIdx.x;

    #pragma unroll
    for (int it = 0; it < 10; it++) {
        int idx = tid + it * 256;
        int i = idx / 5, k = idx - i * 5;
        float v = M[(size_t)i * NMD + o * KDD + k];
        if (k < 4) ((float*)s4)[i * 4 + k] = v;
        else       s1[i] = v;
    }
    __syncthreads();

    const int j = jh * 256 + tid;
    float4 m4 = s4[j];
    float  m4e = s1[j];

    float acc0 = 0.f, acc1 = 0.f;
    #pragma unroll 8
    for (int i = 0; i < BDIM; i++) {
        float4 v = s4[i];
        float  w = s1[i];
        float n = fabsf(v.x - m4.x) + fabsf(v.y - m4.y) + fabsf(v.z - m4.z)
                + fabsf(v.w - m4.w) + fabsf(w - m4e);
        float e;
        asm("ex2.approx.f32 %0, %1;" : "=f"(e) : "f"(-n));
        if (i & 1) acc1 += e; else acc0 += e;
    }
    z[(size_t)j * ZD + H2D + o] = acc0 + acc1 - 1.0f;
}

// ---------------------------------------------------------------------------
__global__ __launch_bounds__(256)
void final_k(const float* __restrict__ z3, const float* __restrict__ W4,
             const float* __restrict__ b4, float* __restrict__ out)
{
    int gw = blockIdx.x * 8 + (threadIdx.x >> 5);
    int lane = threadIdx.x & 31;
    float sum = 0.f;
    #pragma unroll
    for (int it = 0; it < 4; it++)
        sum += z3[(size_t)gw * OUTD + it * 32 + lane] * W4[it * 32 + lane];
    #pragma unroll
    for (int off = 16; off; off >>= 1)
        sum += __shfl_xor_sync(0xffffffffu, sum, off);
    if (lane == 0) out[gw] = sum + b4[0];
}

// ---------------------------------------------------------------------------
extern "C" void kernel_launch(void* const* d_in, const int* in_sizes, int n_in,
                              void* d_out, int out_size)
{
    (void)in_sizes; (void)n_in; (void)out_size;
    const float* x  = (const float*)d_in[0];
    const float* W1 = (const float*)d_in[1];
    const float* b1 = (const float*)d_in[2];
    const float* W2 = (const float*)d_in[3];
    const float* b2 = (const float*)d_in[4];
    const float* T  = (const float*)d_in[5];
    const float* W3 = (const float*)d_in[6];
    const float* b3 = (const float*)d_in[7];
    const float* W4 = (const float*)d_in[8];
    const float* b4 = (const float*)d_in[9];
    float* out = (float*)d_out;

    float *p1, *h1, *p2, *z, *p3, *M, *p4, *z3;
    __nv_bfloat16 *Wbh, *Wbl;
    cudaGetSymbolAddress((void**)&p1, g_p1);
    cudaGetSymbolAddress((void**)&h1, g_h1);
    cudaGetSymbolAddress((void**)&p2, g_p2);
    cudaGetSymbolAddress((void**)&z,  g_z);
    cudaGetSymbolAddress((void**)&p3, g_p3);
    cudaGetSymbolAddress((void**)&M,  g_M);
    cudaGetSymbolAddress((void**)&p4, g_p4);
    cudaGetSymbolAddress((void**)&z3, g_z3);
    cudaGetSymbolAddress((void**)&Wbh, g_Wbh);
    cudaGetSymbolAddress((void**)&Wbl, g_Wbl);

    // Weights -> bf16 hi/lo, transposed [n][k]
    prep_k<<<848, 256>>>(W1, W2, T, W3);

    // GEMM1: x @ W1 -> p1 (split-K=4, Kc=256), grid 8x4x4 = 128 CTAs
    tgemm<<<dim3(8,4,4), 256>>>(x, FDIM, Wbh + WOFF_W1, Wbl + WOFF_W1, FDIM,
                                p1, (size_t)BDIM * H1D, H1D, 256);
    // h1 = lrelu(sum4 + b1)
    reduce_k<4,0><<<256, 256>>>(p1, (size_t)BDIM * H1D, H1D, b1, h1, H1D, 65536);

    // GEMM2: h1 @ W2 -> p2 (split-K=4, Kc=128), grid 4x4x4 = 64 CTAs
    tgemm<<<dim3(4,4,4), 256>>>(h1, H1D, Wbh + WOFF_W2, Wbl + WOFF_W2, H1D,
                                p2, (size_t)BDIM * H2D, H2D, 128);
    // z[:, :256] = lrelu(sum4 + b2)
    reduce_k<4,0><<<128, 256>>>(p2, (size_t)BDIM * H2D, H2D, b2, z, ZD, 32768);

    // GEMM3: h2 @ T -> p3 (split-K=2, Kc=128), grid 10x4x2 = 80 CTAs
    tgemm<<<dim3(10,4,2), 256>>>(z, ZD, Wbh + WOFF_T, Wbl + WOFF_T, H2D,
                                 p3, (size_t)BDIM * NMD, NMD, 128);
    // M = sum2 * log2e
    reduce_k<2,1><<<320, 256>>>(p3, (size_t)BDIM * NMD, NMD, nullptr, M, NMD, 81920);

    // Pairwise -> z[:, 256:]
    pairwise_k<<<dim3(OUTD, 2), 256>>>(M, z);

    // GEMM4: z @ W3 -> p4 (split-K=3, Kc=128), grid 2x4x3 = 24 CTAs
    tgemm<<<dim3(2,4,3), 256>>>(z, ZD, Wbh + WOFF_W3, Wbl + WOFF_W3, ZD,
                                p4, (size_t)BDIM * OUTD, OUTD, 128);
    // z3 = lrelu(sum3 + b3)
    reduce_k<3,0><<<64, 256>>>(p4, (size_t)BDIM * OUTD, OUTD, b3, z3, OUTD, 16384);

    // out = z3 @ W4 + b4
    final_k<<<64, 256>>>(z3, W4, b4, out);
}